// round 5
// baseline (speedup 1.0000x reference)
#include <cuda_runtime.h>
#include <cstdint>

// SyntacticGCN fused kernel for GB300 (sm_103a)
// R5: warp-specialized — 8 reduce warps stream rows sequentially,
//     4 GEMM warps consume 4-row groups in the shadow of the streaming.
// B=16, S=128, M=128, D=256, H=256

#define BB 16
#define SS 128
#define MM 128
#define DD 256
#define HH 256
#define NROWS (BB * SS)   // 2048
#define RPC 8             // rows per CTA
#define GRP 4             // rows per GEMM group
#define NRED 256          // reduce threads (8 warps)
#define NGEM 128          // gemm threads (4 warps)
#define NTHREADS (NRED + NGEM)   // 384

__global__ __launch_bounds__(NTHREADS, 2)
void gcn_fused_kernel(const float* __restrict__ src,
                      const float* __restrict__ ngh,
                      const float* __restrict__ Wm,   // [2D, H] row-major
                      const float* __restrict__ bm,   // [H]
                      float* __restrict__ out)        // [NROWS, H]
{
    __shared__ float    hid[2][GRP][2 * DD];   // double-buffered hidden groups (16 KB)
    __shared__ uint32_t vmask[RPC][4];         // 128-bit validity mask per row

    const int tid  = threadIdx.x;
    const int lane = tid & 31;
    const int row0 = blockIdx.x * RPC;

    if (tid < RPC * 4) ((uint32_t*)vmask)[tid] = 0u;
    __syncthreads();

    if (tid < NRED) {
        // ================= reduce warps: thread t owns column t =================
        const int t = tid;
        for (int r = 0; r < RPC; ++r) {
            const float* sp = src + ((size_t)(row0 + r) * MM) * DD + t;
            const float* np = ngh + ((size_t)(row0 + r) * MM) * DD + t;

            float ssum = 0.f, nsum = 0.f;
            #pragma unroll 2
            for (int c = 0; c < MM / 8; ++c) {        // 16 chunks of 8 m-rows
                uint32_t nzbits = 0;
                float sv[8], nv[8];
                #pragma unroll
                for (int m = 0; m < 8; ++m) {
                    sv[m] = __ldg(sp + (size_t)(c * 8 + m) * DD);
                    nv[m] = __ldg(np + (size_t)(c * 8 + m) * DD);
                }
                #pragma unroll
                for (int m = 0; m < 8; ++m) {
                    ssum += sv[m];
                    nsum += nv[m];
                    nzbits |= (nv[m] != 0.f) ? (1u << m) : 0u;
                }
                uint32_t wor = __reduce_or_sync(0xffffffffu, nzbits);
                if (lane == 0 && wor)
                    atomicOr(&vmask[r][c >> 2], wor << ((c & 3) * 8));
            }

            // all reduce warps done with row r (vmask complete)
            asm volatile("bar.sync 1, %0;" :: "n"(NRED) : "memory");

            int cnt = __popc(vmask[r][0]) + __popc(vmask[r][1]) +
                      __popc(vmask[r][2]) + __popc(vmask[r][3]);
            float inv = 1.0f / fmaxf((float)cnt, 1.0f);

            const int g  = r >> 2;        // group 0: rows 0-3, group 1: rows 4-7
            const int rr = r & 3;
            hid[g][rr][t]      = ssum;
            hid[g][rr][DD + t] = nsum * inv;

            if (rr == GRP - 1) {
                // group complete -> hand to GEMM warps (non-blocking)
                asm volatile("bar.arrive 2, %0;" :: "n"(NTHREADS) : "memory");
            }
        }
        return;   // reduce warps done
    }

    // ================= GEMM warps: 128 threads, thread owns cols j and j+128 ====
    {
        const int jt = tid - NRED;        // 0..127
        const float b0 = __ldg(bm + jt);
        const float b1 = __ldg(bm + jt + 128);

        for (int g = 0; g < RPC / GRP; ++g) {
            // wait for group g's hidden rows (blocks until 256 arrives + 128 syncs)
            asm volatile("bar.sync 2, %0;" :: "n"(NTHREADS) : "memory");

            float acc0[GRP], acc1[GRP];
            #pragma unroll
            for (int rr = 0; rr < GRP; ++rr) { acc0[rr] = b0; acc1[rr] = b1; }

            #pragma unroll 2
            for (int k = 0; k < 2 * DD; k += 4) {
                const float* wrow = Wm + (size_t)k * HH;
                float w00 = __ldg(wrow + jt);
                float w01 = __ldg(wrow + jt + 128);
                float w10 = __ldg(wrow + HH + jt);
                float w11 = __ldg(wrow + HH + jt + 128);
                float w20 = __ldg(wrow + 2 * HH + jt);
                float w21 = __ldg(wrow + 2 * HH + jt + 128);
                float w30 = __ldg(wrow + 3 * HH + jt);
                float w31 = __ldg(wrow + 3 * HH + jt + 128);
                #pragma unroll
                for (int rr = 0; rr < GRP; ++rr) {
                    float4 hv = *(const float4*)&hid[g][rr][k];   // smem broadcast
                    acc0[rr] = fmaf(hv.x, w00, acc0[rr]);
                    acc1[rr] = fmaf(hv.x, w01, acc1[rr]);
                    acc0[rr] = fmaf(hv.y, w10, acc0[rr]);
                    acc1[rr] = fmaf(hv.y, w11, acc1[rr]);
                    acc0[rr] = fmaf(hv.z, w20, acc0[rr]);
                    acc1[rr] = fmaf(hv.z, w21, acc1[rr]);
                    acc0[rr] = fmaf(hv.w, w30, acc0[rr]);
                    acc1[rr] = fmaf(hv.w, w31, acc1[rr]);
                }
            }

            #pragma unroll
            for (int rr = 0; rr < GRP; ++rr) {
                const size_t orow = (size_t)(row0 + g * GRP + rr) * HH;
                float v0 = acc0[rr];
                float v1 = acc1[rr];
                out[orow + jt]       = (v0 > 0.f) ? v0 : 0.01f * v0;
                out[orow + jt + 128] = (v1 > 0.f) ? v1 : 0.01f * v1;
            }
        }
    }
}

extern "C" void kernel_launch(void* const* d_in, const int* in_sizes, int n_in,
                              void* d_out, int out_size)
{
    const float* src = (const float*)d_in[0];   // [B,S,M,D]
    const float* ngh = (const float*)d_in[1];   // [B,S,M,D]
    const float* Wm  = (const float*)d_in[2];   // [2D,H]
    const float* bm  = (const float*)d_in[3];   // [H]
    float* out = (float*)d_out;                 // [B*S, H]

    gcn_fused_kernel<<<NROWS / RPC, NTHREADS>>>(src, ngh, Wm, bm, out);
}

// round 6
// speedup vs baseline: 1.2820x; 1.2820x over previous
#include <cuda_runtime.h>
#include <cstdint>

// SyntacticGCN fused kernel GB300 (sm_103a)
// R6: two 4-row groups; group-0 GEMM interleaved (ILP) into group-1 streaming.
// B=16, S=128, M=128, D=256, H=256

#define MM 128
#define DD 256
#define HH 256
#define NROWS 2048
#define RPC 8
#define GRP 4
#define NTHREADS 256

__global__ __launch_bounds__(NTHREADS, 2)
void gcn_fused_kernel(const float* __restrict__ src,
                      const float* __restrict__ ngh,
                      const float* __restrict__ Wm,   // [2D, H] row-major
                      const float* __restrict__ bm,   // [H]
                      float* __restrict__ out)        // [NROWS, H]
{
    __shared__ float parts[8][2 * DD];        // 16 KB warp partials (reused per group)
    __shared__ float hidg[2][GRP][2 * DD];    // 16 KB hidden, per group
    __shared__ int   cnts[8];

    const int tid  = threadIdx.x;
    const int warp = tid >> 5;
    const int lane = tid & 31;
    const int row0 = blockIdx.x * RPC;
    const int j    = tid;                     // GEMM output column

    // ---------------- group 0: pure streaming (proven shape) ----------------
    {
        const int row  = row0 + (warp >> 1);
        const int half = warp & 1;
        const float4* sp = (const float4*)(src + ((size_t)row * MM + half * (MM / 2)) * DD);
        const float4* np = (const float4*)(ngh + ((size_t)row * MM + half * (MM / 2)) * DD);

        float4 sa0 = {0,0,0,0}, sa1 = {0,0,0,0}, na0 = {0,0,0,0}, na1 = {0,0,0,0};
        int cnt = 0;
        #pragma unroll 4
        for (int i = 0; i < MM / 2; ++i) {
            const int moff = i * (DD / 4);
            float4 s0 = __ldg(sp + moff + lane);
            float4 s1 = __ldg(sp + moff + 32 + lane);
            float4 n0 = __ldg(np + moff + lane);
            float4 n1 = __ldg(np + moff + 32 + lane);
            sa0.x += s0.x; sa0.y += s0.y; sa0.z += s0.z; sa0.w += s0.w;
            sa1.x += s1.x; sa1.y += s1.y; sa1.z += s1.z; sa1.w += s1.w;
            na0.x += n0.x; na0.y += n0.y; na0.z += n0.z; na0.w += n0.w;
            na1.x += n1.x; na1.y += n1.y; na1.z += n1.z; na1.w += n1.w;
            bool nz = (n0.x != 0.f) | (n0.y != 0.f) | (n0.z != 0.f) | (n0.w != 0.f) |
                      (n1.x != 0.f) | (n1.y != 0.f) | (n1.z != 0.f) | (n1.w != 0.f);
            if (__any_sync(0xffffffffu, nz)) cnt++;
        }
        float4* dst = (float4*)&parts[warp][0];
        dst[lane] = sa0; dst[32 + lane] = sa1; dst[64 + lane] = na0; dst[96 + lane] = na1;
        if (lane == 0) cnts[warp] = cnt;
    }
    __syncthreads();
    // combine group 0 -> hidg[0]
    #pragma unroll
    for (int i = 0; i < (GRP * 2 * DD) / NTHREADS; ++i) {
        const int idx = tid + i * NTHREADS;           // 0..2047
        const int rr  = idx >> 9, k = idx & (2 * DD - 1);
        float v = parts[2 * rr][k] + parts[2 * rr + 1][k];
        if (k >= DD) {
            float c = (float)(cnts[2 * rr] + cnts[2 * rr + 1]);
            v *= 1.0f / fmaxf(c, 1.0f);
        }
        hidg[0][rr][k] = v;
    }
    __syncthreads();

    // ------ group 1 streaming + interleaved GEMM strip for group 0 ------
    const float bj = __ldg(bm + j);
    float g0a0 = bj, g0a1 = bj, g0a2 = bj, g0a3 = bj;   // strip accumulators (rows 0..3)
    {
        const int row  = row0 + GRP + (warp >> 1);
        const int half = warp & 1;
        const float4* sp = (const float4*)(src + ((size_t)row * MM + half * (MM / 2)) * DD);
        const float4* np = (const float4*)(ngh + ((size_t)row * MM + half * (MM / 2)) * DD);

        float4 sa0 = {0,0,0,0}, sa1 = {0,0,0,0}, na0 = {0,0,0,0}, na1 = {0,0,0,0};
        int cnt = 0;
        for (int i = 0; i < MM / 2; ++i) {              // 64 iters; k0 = 8*i covers 0..511
            const int moff = i * (DD / 4);
            // issue independent streaming loads first
            float4 s0 = __ldg(sp + moff + lane);
            float4 s1 = __ldg(sp + moff + 32 + lane);
            float4 n0 = __ldg(np + moff + lane);
            float4 n1 = __ldg(np + moff + 32 + lane);

            // --- GEMM strip: 8 k-steps x 4 rows while loads are in flight ---
            const int k0 = i * 8;
            const float* wp = Wm + (size_t)k0 * HH + j;
            float w0 = __ldg(wp);
            float w1 = __ldg(wp + HH);
            float w2 = __ldg(wp + 2 * HH);
            float w3 = __ldg(wp + 3 * HH);
            float w4 = __ldg(wp + 4 * HH);
            float w5 = __ldg(wp + 5 * HH);
            float w6 = __ldg(wp + 6 * HH);
            float w7 = __ldg(wp + 7 * HH);
            #pragma unroll
            for (int rr = 0; rr < GRP; ++rr) {
                float4 h0 = *(const float4*)&hidg[0][rr][k0];       // broadcast
                float4 h1 = *(const float4*)&hidg[0][rr][k0 + 4];
                float a = (rr == 0) ? g0a0 : (rr == 1) ? g0a1 : (rr == 2) ? g0a2 : g0a3;
                a = fmaf(h0.x, w0, a); a = fmaf(h0.y, w1, a);
                a = fmaf(h0.z, w2, a); a = fmaf(h0.w, w3, a);
                a = fmaf(h1.x, w4, a); a = fmaf(h1.y, w5, a);
                a = fmaf(h1.z, w6, a); a = fmaf(h1.w, w7, a);
                if      (rr == 0) g0a0 = a;
                else if (rr == 1) g0a1 = a;
                else if (rr == 2) g0a2 = a;
                else              g0a3 = a;
            }

            // --- consume streaming loads ---
            sa0.x += s0.x; sa0.y += s0.y; sa0.z += s0.z; sa0.w += s0.w;
            sa1.x += s1.x; sa1.y += s1.y; sa1.z += s1.z; sa1.w += s1.w;
            na0.x += n0.x; na0.y += n0.y; na0.z += n0.z; na0.w += n0.w;
            na1.x += n1.x; na1.y += n1.y; na1.z += n1.z; na1.w += n1.w;
            bool nz = (n0.x != 0.f) | (n0.y != 0.f) | (n0.z != 0.f) | (n0.w != 0.f) |
                      (n1.x != 0.f) | (n1.y != 0.f) | (n1.z != 0.f) | (n1.w != 0.f);
            if (__any_sync(0xffffffffu, nz)) cnt++;
        }
        float4* dst = (float4*)&parts[warp][0];
        dst[lane] = sa0; dst[32 + lane] = sa1; dst[64 + lane] = na0; dst[96 + lane] = na1;
        if (lane == 0) cnts[warp] = cnt;
    }
    // store group-0 outputs (no sync needed; global writes)
    {
        float v;
        v = g0a0; out[(size_t)(row0 + 0) * HH + j] = (v > 0.f) ? v : 0.01f * v;
        v = g0a1; out[(size_t)(row0 + 1) * HH + j] = (v > 0.f) ? v : 0.01f * v;
        v = g0a2; out[(size_t)(row0 + 2) * HH + j] = (v > 0.f) ? v : 0.01f * v;
        v = g0a3; out[(size_t)(row0 + 3) * HH + j] = (v > 0.f) ? v : 0.01f * v;
    }
    __syncthreads();
    // combine group 1 -> hidg[1]
    #pragma unroll
    for (int i = 0; i < (GRP * 2 * DD) / NTHREADS; ++i) {
        const int idx = tid + i * NTHREADS;
        const int rr  = idx >> 9, k = idx & (2 * DD - 1);
        float v = parts[2 * rr][k] + parts[2 * rr + 1][k];
        if (k >= DD) {
            float c = (float)(cnts[2 * rr] + cnts[2 * rr + 1]);
            v *= 1.0f / fmaxf(c, 1.0f);
        }
        hidg[1][rr][k] = v;
    }
    __syncthreads();

    // ---------------- exposed GEMM: group 1 only ----------------
    {
        float a0 = bj, a1 = bj, a2 = bj, a3 = bj;
        #pragma unroll 2
        for (int k = 0; k < 2 * DD; k += 4) {
            const float* wp = Wm + (size_t)k * HH + j;
            float w0 = __ldg(wp);
            float w1 = __ldg(wp + HH);
            float w2 = __ldg(wp + 2 * HH);
            float w3 = __ldg(wp + 3 * HH);
            float4 h0 = *(const float4*)&hidg[1][0][k];
            float4 h1 = *(const float4*)&hidg[1][1][k];
            float4 h2 = *(const float4*)&hidg[1][2][k];
            float4 h3 = *(const float4*)&hidg[1][3][k];
            a0 = fmaf(h0.x, w0, a0); a0 = fmaf(h0.y, w1, a0); a0 = fmaf(h0.z, w2, a0); a0 = fmaf(h0.w, w3, a0);
            a1 = fmaf(h1.x, w0, a1); a1 = fmaf(h1.y, w1, a1); a1 = fmaf(h1.z, w2, a1); a1 = fmaf(h1.w, w3, a1);
            a2 = fmaf(h2.x, w0, a2); a2 = fmaf(h2.y, w1, a2); a2 = fmaf(h2.z, w2, a2); a2 = fmaf(h2.w, w3, a2);
            a3 = fmaf(h3.x, w0, a3); a3 = fmaf(h3.y, w1, a3); a3 = fmaf(h3.z, w2, a3); a3 = fmaf(h3.w, w3, a3);
        }
        float v;
        v = a0; out[(size_t)(row0 + 4) * HH + j] = (v > 0.f) ? v : 0.01f * v;
        v = a1; out[(size_t)(row0 + 5) * HH + j] = (v > 0.f) ? v : 0.01f * v;
        v = a2; out[(size_t)(row0 + 6) * HH + j] = (v > 0.f) ? v : 0.01f * v;
        v = a3; out[(size_t)(row0 + 7) * HH + j] = (v > 0.f) ? v : 0.01f * v;
    }
}

extern "C" void kernel_launch(void* const* d_in, const int* in_sizes, int n_in,
                              void* d_out, int out_size)
{
    const float* src = (const float*)d_in[0];   // [B,S,M,D]
    const float* ngh = (const float*)d_in[1];   // [B,S,M,D]
    const float* Wm  = (const float*)d_in[2];   // [2D,H]
    const float* bm  = (const float*)d_in[3];   // [H]
    float* out = (float*)d_out;                 // [B*S, H]

    gcn_fused_kernel<<<NROWS / RPC, NTHREADS>>>(src, ngh, Wm, bm, out);
}

// round 7
// speedup vs baseline: 1.3559x; 1.0576x over previous
#include <cuda_runtime.h>

// SyntacticGCN fused kernel GB300 (sm_103a)
// R7: exact one-wave even partition — 296 CTAs (2/SM), 6-7 rows each.
// B=16, S=128, M=128, D=256, H=256

#define MM 128
#define DD 256
#define HH 256
#define NROWS 2048
#define NCTAS 296          // 2 * 148 SMs, exactly one wave at occ 2
#define RMAX 7             // max rows per CTA
#define NTHREADS 256

__global__ __launch_bounds__(NTHREADS, 2)
void gcn_fused_kernel(const float* __restrict__ src,
                      const float* __restrict__ ngh,
                      const float* __restrict__ Wm,   // [2D, H] row-major
                      const float* __restrict__ bm,   // [H]
                      float* __restrict__ out)        // [NROWS, H]
{
    __shared__ float parts[8][2 * DD];     // 16 KB warp partials
    __shared__ float hid[RMAX][2 * DD];    // 14 KB hidden rows
    __shared__ int   cnts[8];

    const int tid  = threadIdx.x;
    const int warp = tid >> 5;
    const int lane = tid & 31;

    const int r0 = (blockIdx.x * NROWS) / NCTAS;
    const int r1 = ((blockIdx.x + 1) * NROWS) / NCTAS;
    const int nr = r1 - r0;                // 6 or 7

    // ---------------- Phase 1: row-sequential streaming ----------------
    // warp w owns m in [16w, 16w+16); lane owns cols [4*lane,4*lane+4) and +128.
    for (int r = 0; r < nr; ++r) {
        const int row = r0 + r;
        const float4* sp = (const float4*)(src + (size_t)row * MM * DD);
        const float4* np = (const float4*)(ngh + (size_t)row * MM * DD);

        float4 sa0 = {0,0,0,0}, sa1 = {0,0,0,0}, na0 = {0,0,0,0}, na1 = {0,0,0,0};
        int cnt = 0;

        const int mbase = warp * 16;
        #pragma unroll 4
        for (int i = 0; i < 16; ++i) {
            const int moff = (mbase + i) * (DD / 4);
            // each LDG.128: 32 lanes x 16B contiguous = 4 full 128B lines
            float4 s0 = __ldg(sp + moff + lane);        // cols [0,128)
            float4 s1 = __ldg(sp + moff + 32 + lane);   // cols [128,256)
            float4 n0 = __ldg(np + moff + lane);
            float4 n1 = __ldg(np + moff + 32 + lane);

            sa0.x += s0.x; sa0.y += s0.y; sa0.z += s0.z; sa0.w += s0.w;
            sa1.x += s1.x; sa1.y += s1.y; sa1.z += s1.z; sa1.w += s1.w;
            na0.x += n0.x; na0.y += n0.y; na0.z += n0.z; na0.w += n0.w;
            na1.x += n1.x; na1.y += n1.y; na1.z += n1.z; na1.w += n1.w;

            bool nz = (n0.x != 0.f) | (n0.y != 0.f) | (n0.z != 0.f) | (n0.w != 0.f) |
                      (n1.x != 0.f) | (n1.y != 0.f) | (n1.z != 0.f) | (n1.w != 0.f);
            if (__any_sync(0xffffffffu, nz)) cnt++;
        }

        float4* dst = (float4*)&parts[warp][0];
        dst[lane]      = sa0;   // src cols [0,128)
        dst[32 + lane] = sa1;   // src cols [128,256)
        dst[64 + lane] = na0;   // neigh cols [0,128)
        dst[96 + lane] = na1;   // neigh cols [128,256)
        if (lane == 0) cnts[warp] = cnt;
        __syncthreads();

        // combine: thread t owns src col t and neigh col t
        float ssum = 0.f, nsum = 0.f;
        #pragma unroll
        for (int w = 0; w < 8; ++w) {
            ssum += parts[w][tid];
            nsum += parts[w][DD + tid];
        }
        int ctot = 0;
        #pragma unroll
        for (int w = 0; w < 8; ++w) ctot += cnts[w];
        float inv = 1.0f / fmaxf((float)ctot, 1.0f);

        hid[r][tid]      = ssum;
        hid[r][DD + tid] = nsum * inv;
        __syncthreads();   // parts reused next row
    }

    // ---------------- Phase 2: GEMM + bias + leaky_relu ----------------
    const int j = tid;
    float acc[RMAX];
    const float bj = __ldg(bm + j);
    #pragma unroll
    for (int r = 0; r < RMAX; ++r) acc[r] = bj;

    #pragma unroll 2
    for (int k = 0; k < 2 * DD; k += 4) {
        const float* wp = Wm + (size_t)k * HH + j;
        float w0 = __ldg(wp);
        float w1 = __ldg(wp + HH);
        float w2 = __ldg(wp + 2 * HH);
        float w3 = __ldg(wp + 3 * HH);
        #pragma unroll
        for (int r = 0; r < RMAX; ++r) {
            float4 h = *(const float4*)&hid[r][k];   // smem broadcast
            acc[r] = fmaf(h.x, w0, acc[r]);
            acc[r] = fmaf(h.y, w1, acc[r]);
            acc[r] = fmaf(h.z, w2, acc[r]);
            acc[r] = fmaf(h.w, w3, acc[r]);
        }
    }

    #pragma unroll
    for (int r = 0; r < RMAX; ++r) {
        if (r < nr) {
            float v = acc[r];
            out[(size_t)(r0 + r) * HH + j] = (v > 0.f) ? v : 0.01f * v;
        }
    }
}

extern "C" void kernel_launch(void* const* d_in, const int* in_sizes, int n_in,
                              void* d_out, int out_size)
{
    const float* src = (const float*)d_in[0];   // [B,S,M,D]
    const float* ngh = (const float*)d_in[1];   // [B,S,M,D]
    const float* Wm  = (const float*)d_in[2];   // [2D,H]
    const float* bm  = (const float*)d_in[3];   // [H]
    float* out = (float*)d_out;                 // [B*S, H]

    gcn_fused_kernel<<<NCTAS, NTHREADS>>>(src, ngh, Wm, bm, out);
}

// round 8
// speedup vs baseline: 1.5861x; 1.1698x over previous
#include <cuda_runtime.h>

// SyntacticGCN fused kernel GB300 (sm_103a)
// R8: R7 streaming (296 CTAs, even partition) + FFMA2 (f32x2) GEMM tail
// B=16, S=128, M=128, D=256, H=256

#define MM 128
#define DD 256
#define HH 256
#define NROWS 2048
#define NCTAS 296
#define RMAX 7
#define NTHREADS 256

__device__ __forceinline__ double pack2(float a) {
    double d;
    asm("mov.b64 %0, {%1, %1};" : "=d"(d) : "f"(a));
    return d;
}
__device__ __forceinline__ double fma2(double a, double b, double c) {
    double d;
    asm("fma.rn.f32x2 %0, %1, %2, %3;" : "=d"(d) : "d"(a), "d"(b), "d"(c));
    return d;
}

__global__ __launch_bounds__(NTHREADS, 2)
void gcn_fused_kernel(const float* __restrict__ src,
                      const float* __restrict__ ngh,
                      const float* __restrict__ Wm,   // [2D, H] row-major
                      const float* __restrict__ bm,   // [H]
                      float* __restrict__ out)        // [NROWS, H]
{
    // pool: phase-1 warp partials (16 KB) ALIASED with GEMM k-split buffer (28 KB)
    __shared__ __align__(16) char pool[4 * RMAX * 64 * 16];   // 28672 B
    __shared__ float hid[RMAX][2 * DD];                        // 14 KB
    __shared__ int   cnts[8];

    float (*parts)[2 * DD] = (float (*)[2 * DD])pool;
    double2* buf = (double2*)pool;           // [kq][r][jq] : 4*7*64 double2

    const int tid  = threadIdx.x;
    const int warp = tid >> 5;
    const int lane = tid & 31;

    const int r0 = (blockIdx.x * NROWS) / NCTAS;
    const int r1 = ((blockIdx.x + 1) * NROWS) / NCTAS;
    const int nr = r1 - r0;                  // 6 or 7

    // ---------------- Phase 1: row-sequential streaming (R7, unchanged) ----------------
    for (int r = 0; r < nr; ++r) {
        const int row = r0 + r;
        const float4* sp = (const float4*)(src + (size_t)row * MM * DD);
        const float4* np = (const float4*)(ngh + (size_t)row * MM * DD);

        float4 sa0 = {0,0,0,0}, sa1 = {0,0,0,0}, na0 = {0,0,0,0}, na1 = {0,0,0,0};
        int cnt = 0;

        const int mbase = warp * 16;
        #pragma unroll 4
        for (int i = 0; i < 16; ++i) {
            const int moff = (mbase + i) * (DD / 4);
            float4 s0 = __ldg(sp + moff + lane);
            float4 s1 = __ldg(sp + moff + 32 + lane);
            float4 n0 = __ldg(np + moff + lane);
            float4 n1 = __ldg(np + moff + 32 + lane);

            sa0.x += s0.x; sa0.y += s0.y; sa0.z += s0.z; sa0.w += s0.w;
            sa1.x += s1.x; sa1.y += s1.y; sa1.z += s1.z; sa1.w += s1.w;
            na0.x += n0.x; na0.y += n0.y; na0.z += n0.z; na0.w += n0.w;
            na1.x += n1.x; na1.y += n1.y; na1.z += n1.z; na1.w += n1.w;

            bool nz = (n0.x != 0.f) | (n0.y != 0.f) | (n0.z != 0.f) | (n0.w != 0.f) |
                      (n1.x != 0.f) | (n1.y != 0.f) | (n1.z != 0.f) | (n1.w != 0.f);
            if (__any_sync(0xffffffffu, nz)) cnt++;
        }

        float4* dst = (float4*)&parts[warp][0];
        dst[lane]      = sa0;
        dst[32 + lane] = sa1;
        dst[64 + lane] = na0;
        dst[96 + lane] = na1;
        if (lane == 0) cnts[warp] = cnt;
        __syncthreads();

        float ssum = 0.f, nsum = 0.f;
        #pragma unroll
        for (int w = 0; w < 8; ++w) {
            ssum += parts[w][tid];
            nsum += parts[w][DD + tid];
        }
        int ctot = 0;
        #pragma unroll
        for (int w = 0; w < 8; ++w) ctot += cnts[w];
        float inv = 1.0f / fmaxf((float)ctot, 1.0f);

        hid[r][tid]      = ssum;
        hid[r][DD + tid] = nsum * inv;
        __syncthreads();   // parts reused next row; after last row, pool free for buf
    }
    // zero unused hid row so FFMA2 on it stays finite-but-unused garbage-free
    if (nr < RMAX) {
        hid[nr][tid]      = 0.f;
        hid[nr][DD + tid] = 0.f;
    }
    __syncthreads();

    // ---------------- Phase 2: FFMA2 GEMM, k-split x4 ----------------
    // thread = (jq, kq): j columns [4jq, 4jq+4), k range [128*kq, 128*kq+128)
    const int jq = tid & 63;
    const int kq = tid >> 6;
    const int k0 = kq * 128;

    double a01[RMAX], a23[RMAX];   // f32x2 accumulators: {j0,j1}, {j2,j3}
    #pragma unroll
    for (int r = 0; r < RMAX; ++r) { a01[r] = 0.0; a23[r] = 0.0; }

    #pragma unroll 1
    for (int k = 0; k < 128; k += 4) {
        // W rows k0+k .. k0+k+3, 4 j-columns each: LDG.128 as double2 (f32x2 pairs)
        const float* wb = Wm + (size_t)(k0 + k) * HH + 4 * jq;
        double2 w0 = __ldg((const double2*)(wb));
        double2 w1 = __ldg((const double2*)(wb + HH));
        double2 w2 = __ldg((const double2*)(wb + 2 * HH));
        double2 w3 = __ldg((const double2*)(wb + 3 * HH));

        #pragma unroll
        for (int r = 0; r < RMAX; ++r) {
            float4 h = *(const float4*)&hid[r][k0 + k];   // smem broadcast
            double h0 = pack2(h.x), h1 = pack2(h.y), h2 = pack2(h.z), h3 = pack2(h.w);
            a01[r] = fma2(h0, w0.x, a01[r]);  a23[r] = fma2(h0, w0.y, a23[r]);
            a01[r] = fma2(h1, w1.x, a01[r]);  a23[r] = fma2(h1, w1.y, a23[r]);
            a01[r] = fma2(h2, w2.x, a01[r]);  a23[r] = fma2(h2, w2.y, a23[r]);
            a01[r] = fma2(h3, w3.x, a01[r]);  a23[r] = fma2(h3, w3.y, a23[r]);
        }
    }

    // stage k-split partials: buf[kq][r][jq] = {j0,j1,j2,j3}  (STS.128, conflict-free)
    #pragma unroll
    for (int r = 0; r < RMAX; ++r)
        buf[(kq * RMAX + r) * 64 + jq] = make_double2(a01[r], a23[r]);
    __syncthreads();

    // ---------------- reduce kq partials + bias + leaky_relu ----------------
    {
        const int j  = tid;
        const float bj = __ldg(bm + j);
        const float* bf = (const float*)buf;
        const int base = (j >> 2) * 4 + (j & 3);   // = j  (within a [64][4] float block)
        #pragma unroll
        for (int r = 0; r < RMAX; ++r) {
            if (r < nr) {
                float v = bj;
                #pragma unroll
                for (int q = 0; q < 4; ++q)
                    v += bf[(q * RMAX + r) * 256 + base];
                out[(size_t)(r0 + r) * HH + j] = (v > 0.f) ? v : 0.01f * v;
            }
        }
    }
}

extern "C" void kernel_launch(void* const* d_in, const int* in_sizes, int n_in,
                              void* d_out, int out_size)
{
    const float* src = (const float*)d_in[0];   // [B,S,M,D]
    const float* ngh = (const float*)d_in[1];   // [B,S,M,D]
    const float* Wm  = (const float*)d_in[2];   // [2D,H]
    const float* bm  = (const float*)d_in[3];   // [H]
    float* out = (float*)d_out;                 // [B*S, H]

    gcn_fused_kernel<<<NCTAS, NTHREADS>>>(src, ngh, Wm, bm, out);
}